// round 1
// baseline (speedup 1.0000x reference)
#include <cuda_runtime.h>
#include <math.h>

#define S_ 128
#define N_ 256
#define D_ 256
#define H_ 8
#define DH_ 32
#define FF_ 1024
#define NL_ 3
#define SN_ (S_ * N_)   // 32768

// ---------------- scratch (device globals; no allocation allowed) -------------
__device__ float g_h[SN_ * D_];          // hidden state       33.5 MB
__device__ float g_qkv[SN_ * 3 * D_];    // qkv projections   100.7 MB
__device__ float g_attn[SN_ * D_];       // attention output   33.5 MB
__device__ float g_ff[SN_ * FF_];        // ff1 activations   134.2 MB
__device__ float g_tmp[SN_ * D_];        // o2 / ff2 output    33.5 MB
__device__ float g_nodes[N_ * S_ * D_];  // (N,S,D)            33.5 MB
__device__ float g_gk[N_ * S_ * D_];
__device__ float g_gv[N_ * S_ * D_];
__device__ float g_pk[N_ * S_ * D_];
__device__ float g_graph[N_ * D_];
__device__ float g_qgraph[N_ * D_];
__device__ float g_prev[N_ * D_];
__device__ float g_first[N_ * D_];
__device__ int   g_maskdec[N_ * S_];

// ---------------- generic fp32 GEMM: C = A(MxK) * B(KxN) (+bias, relu) -------
// 64x64 block tile, 16 k-slice, 256 threads, 4x4 per thread.
__global__ __launch_bounds__(256) void sgemm_kernel(
    const float* __restrict__ A, const float* __restrict__ B,
    const float* __restrict__ bias, float* __restrict__ C,
    int M, int N, int K, int relu)
{
    __shared__ float As[16][68];
    __shared__ float Bs[16][68];
    const int tid = threadIdx.x;
    const int tx = tid & 15;
    const int ty = tid >> 4;
    const int rowBase = blockIdx.y * 64;
    const int colBase = blockIdx.x * 64;

    const int aRow = tid >> 2;           // 0..63
    const int aCol = (tid & 3) << 2;     // 0,4,8,12
    const int bRow = tid >> 4;           // 0..15
    const int bCol = (tid & 15) << 2;    // 0..60

    const float* Aptr = A + (size_t)(rowBase + aRow) * K + aCol;
    const float* Bptr = B + (size_t)bRow * N + colBase + bCol;

    float acc[4][4] = {};

    for (int kt = 0; kt < K; kt += 16) {
        float4 av = *(const float4*)(Aptr + kt);
        As[aCol + 0][aRow] = av.x;
        As[aCol + 1][aRow] = av.y;
        As[aCol + 2][aRow] = av.z;
        As[aCol + 3][aRow] = av.w;
        float4 bv = *(const float4*)(Bptr + (size_t)kt * N);
        *(float4*)&Bs[bRow][bCol] = bv;
        __syncthreads();
#pragma unroll
        for (int kk = 0; kk < 16; kk++) {
            float4 a4 = *(const float4*)&As[kk][ty << 2];
            float4 b4 = *(const float4*)&Bs[kk][tx << 2];
            acc[0][0] += a4.x * b4.x; acc[0][1] += a4.x * b4.y;
            acc[0][2] += a4.x * b4.z; acc[0][3] += a4.x * b4.w;
            acc[1][0] += a4.y * b4.x; acc[1][1] += a4.y * b4.y;
            acc[1][2] += a4.y * b4.z; acc[1][3] += a4.y * b4.w;
            acc[2][0] += a4.z * b4.x; acc[2][1] += a4.z * b4.y;
            acc[2][2] += a4.z * b4.z; acc[2][3] += a4.z * b4.w;
            acc[3][0] += a4.w * b4.x; acc[3][1] += a4.w * b4.y;
            acc[3][2] += a4.w * b4.z; acc[3][3] += a4.w * b4.w;
        }
        __syncthreads();
    }

#pragma unroll
    for (int i = 0; i < 4; i++) {
        int row = rowBase + (ty << 2) + i;
#pragma unroll
        for (int j = 0; j < 4; j++) {
            int col = colBase + (tx << 2) + j;
            float v = acc[i][j];
            if (bias) v += bias[col];
            if (relu) v = fmaxf(v, 0.f);
            C[(size_t)row * N + col] = v;
        }
    }
}

// ---------------- encoder self-attention -------------------------------------
// One block per (n, h); 128 threads, one query row each.
__global__ __launch_bounds__(128) void enc_attn_kernel(
    const float* __restrict__ qkv, const int* __restrict__ mask,
    float* __restrict__ out)
{
    const int n = blockIdx.x >> 3;
    const int h = blockIdx.x & 7;
    const int tid = threadIdx.x;   // query row

    __shared__ float Ks[128][36];
    __shared__ float Vs[128][36];
    __shared__ int pad[128];

    const float* base = qkv + ((size_t)tid * N_ + n) * (3 * D_) + h * DH_;
#pragma unroll
    for (int j = 0; j < DH_; j += 4) {
        *(float4*)&Ks[tid][j] = *(const float4*)(base + D_ + j);
        *(float4*)&Vs[tid][j] = *(const float4*)(base + 2 * D_ + j);
    }
    pad[tid] = (mask[n * S_ + tid] == 0);

    float q[DH_];
#pragma unroll
    for (int j = 0; j < DH_; j++) q[j] = base[j];
    __syncthreads();

    float scrow[S_];
    float m = -3.4e38f;
    for (int s = 0; s < S_; s++) {
        float d = 0.f;
#pragma unroll
        for (int j = 0; j < DH_; j++) d += q[j] * Ks[s][j];
        d *= 0.17677669529663687f;   // 1/sqrt(32)
        if (pad[s]) d = -1e9f;
        scrow[s] = d;
        m = fmaxf(m, d);
    }
    float ssum = 0.f;
    for (int s = 0; s < S_; s++) {
        float e = expf(scrow[s] - m);
        scrow[s] = e;
        ssum += e;
    }
    float o[DH_] = {};
    for (int s = 0; s < S_; s++) {
        float w = scrow[s];
#pragma unroll
        for (int j = 0; j < DH_; j++) o[j] += w * Vs[s][j];
    }
    const float inv = 1.f / ssum;
    float* op = out + ((size_t)tid * N_ + n) * D_ + h * DH_;
#pragma unroll
    for (int j = 0; j < DH_; j++) op[j] = o[j] * inv;
}

// ---------------- residual + LayerNorm ---------------------------------------
__global__ __launch_bounds__(256) void add_ln_kernel(
    const float* __restrict__ x, const float* __restrict__ r,
    const float* __restrict__ gam, const float* __restrict__ bet,
    float* __restrict__ out)
{
    const int row = blockIdx.x, tid = threadIdx.x;
    const size_t off = (size_t)row * D_ + tid;
    float v = x[off] + r[off];

    __shared__ float red[8];
    float s = v;
#pragma unroll
    for (int o = 16; o; o >>= 1) s += __shfl_xor_sync(0xffffffffu, s, o);
    if ((tid & 31) == 0) red[tid >> 5] = s;
    __syncthreads();
    if (tid < 32) {
        float t = (tid < 8) ? red[tid] : 0.f;
#pragma unroll
        for (int o = 4; o; o >>= 1) t += __shfl_xor_sync(0xffffffffu, t, o);
        if (tid == 0) red[0] = t;
    }
    __syncthreads();
    const float mu = red[0] * (1.f / D_);
    __syncthreads();

    const float d = v - mu;
    float s2 = d * d;
#pragma unroll
    for (int o = 16; o; o >>= 1) s2 += __shfl_xor_sync(0xffffffffu, s2, o);
    if ((tid & 31) == 0) red[tid >> 5] = s2;
    __syncthreads();
    if (tid < 32) {
        float t = (tid < 8) ? red[tid] : 0.f;
#pragma unroll
        for (int o = 4; o; o >>= 1) t += __shfl_xor_sync(0xffffffffu, t, o);
        if (tid == 0) red[0] = t;
    }
    __syncthreads();
    const float var = red[0] * (1.f / D_);
    out[off] = d * rsqrtf(var + 1e-5f) * gam[tid] + bet[tid];
}

// ---------------- transpose (S,N,D) -> (N,S,D) and graph mean ----------------
__global__ __launch_bounds__(256) void transpose_kernel(const float* __restrict__ h)
{
    const int b = blockIdx.x;         // s*N + n
    const int s = b >> 8;
    const int n = b & 255;
    g_nodes[((size_t)(n * S_ + s)) * D_ + threadIdx.x] =
        h[(size_t)b * D_ + threadIdx.x];
}

__global__ __launch_bounds__(256) void mean_kernel()
{
    const int n = blockIdx.x, tid = threadIdx.x;
    float s = 0.f;
    for (int j = 0; j < S_; j++)
        s += g_nodes[((size_t)(n * S_ + j)) * D_ + tid];
    g_graph[n * D_ + tid] = s * (1.f / S_);
}

// ---------------- decode init -------------------------------------------------
__global__ __launch_bounds__(256) void decode_init_kernel(
    const float* __restrict__ v1, const float* __restrict__ v2,
    const int* __restrict__ mask, float* __restrict__ lps)
{
    const int n = blockIdx.x, tid = threadIdx.x;
    g_prev[n * D_ + tid] = v2[tid];
    g_first[n * D_ + tid] = v1[tid];
    if (tid < S_) g_maskdec[n * S_ + tid] = (mask[n * S_ + tid] == 0);
    if (tid == 0) lps[n] = 0.f;
}

// ---------------- fused decode step (one block per batch item n) --------------
__global__ __launch_bounds__(256) void decode_step_kernel(
    const float* __restrict__ wq, const float* __restrict__ wo,
    const float* __restrict__ bo, const float* __restrict__ pwq,
    float* __restrict__ lps, int t)
{
    const int n = blockIdx.x, tid = threadIdx.x;
    __shared__ float sh_prev[D_], sh_first[D_], sh_q[D_], sh_v[D_], sh_v2[D_];
    __shared__ float sh_att[H_ * S_];
    __shared__ float sh_lg[S_];
    __shared__ int sh_idx;

    sh_prev[tid]  = g_prev[n * D_ + tid];
    sh_first[tid] = g_first[n * D_ + tid];
    __syncthreads();

    // q = q_graph + prev @ Wq[D:2D] + first @ Wq[2D:3D]
    {
        const float* Wp = wq + D_ * D_;
        const float* Wf = wq + 2 * D_ * D_;
        float acc = g_qgraph[n * D_ + tid];
#pragma unroll 4
        for (int k = 0; k < D_; k++)
            acc += sh_prev[k] * Wp[k * D_ + tid] + sh_first[k] * Wf[k * D_ + tid];
        sh_q[tid] = acc;
    }
    __syncthreads();

    // attention scores: (h, s)
    const float* gkb = g_gk + (size_t)n * S_ * D_;
    for (int p = tid; p < H_ * S_; p += 256) {
        const int hh = p >> 7;
        const int s = p & (S_ - 1);
        const float* kp = gkb + s * D_ + hh * DH_;
        float d = 0.f;
#pragma unroll
        for (int j = 0; j < DH_; j++) d += sh_q[hh * DH_ + j] * kp[j];
        d *= 0.17677669529663687f;
        if (g_maskdec[n * S_ + s]) d = -1e9f;
        sh_att[hh * S_ + s] = d;
    }
    __syncthreads();

    // softmax per head: warp w handles head w
    {
        const int w = tid >> 5, lane = tid & 31;
        float vals[4];
        float m = -3.4e38f;
#pragma unroll
        for (int i = 0; i < 4; i++) {
            vals[i] = sh_att[w * S_ + lane + i * 32];
            m = fmaxf(m, vals[i]);
        }
#pragma unroll
        for (int o = 16; o; o >>= 1) m = fmaxf(m, __shfl_xor_sync(0xffffffffu, m, o));
        float ssum = 0.f;
#pragma unroll
        for (int i = 0; i < 4; i++) { vals[i] = expf(vals[i] - m); ssum += vals[i]; }
#pragma unroll
        for (int o = 16; o; o >>= 1) ssum += __shfl_xor_sync(0xffffffffu, ssum, o);
        const float inv = 1.f / ssum;
#pragma unroll
        for (int i = 0; i < 4; i++) sh_att[w * S_ + lane + i * 32] = vals[i] * inv;
    }
    __syncthreads();

    // att @ gv  -> (D,)
    {
        const int hh = tid >> 5;
        const float* gvb = g_gv + (size_t)n * S_ * D_ + tid;
        float a = 0.f;
#pragma unroll 4
        for (int s = 0; s < S_; s++) a += sh_att[hh * S_ + s] * gvb[s * D_];
        sh_v[tid] = a;
    }
    __syncthreads();

    // gl = attnout @ g_wo + g_bo
    {
        float g = bo[tid];
#pragma unroll 4
        for (int k = 0; k < D_; k++) g += sh_v[k] * wo[k * D_ + tid];
        sh_v2[tid] = g;
    }
    __syncthreads();

    // ql = gl @ p_wq / sqrt(D)
    {
        float qv = 0.f;
#pragma unroll 4
        for (int k = 0; k < D_; k++) qv += sh_v2[k] * pwq[k * D_ + tid];
        sh_q[tid] = qv * 0.0625f;
    }
    __syncthreads();

    // pointer logits
    if (tid < S_) {
        const float4* pkr = (const float4*)(g_pk + ((size_t)n * S_ + tid) * D_);
        const float4* qr = (const float4*)sh_q;
        float d = 0.f;
#pragma unroll 8
        for (int j = 0; j < D_ / 4; j++) {
            float4 a4 = pkr[j], b4 = qr[j];
            d += a4.x * b4.x + a4.y * b4.y + a4.z * b4.z + a4.w * b4.w;
        }
        float lg = 10.f * tanhf(d);
        if (g_maskdec[n * S_ + tid]) lg = -1e9f;
        sh_lg[tid] = lg;
    }
    __syncthreads();

    // argmax (first-max, matching jnp.argmax) + log_softmax + state update
    if (tid == 0) {
        float m = -3.4e38f;
        int bi = 0;
        for (int s = 0; s < S_; s++)
            if (sh_lg[s] > m) { m = sh_lg[s]; bi = s; }
        float ssum = 0.f;
        for (int s = 0; s < S_; s++) ssum += expf(sh_lg[s] - m);
        const float lp = sh_lg[bi] - m - logf(ssum);
        lps[n] += lp;
        g_maskdec[n * S_ + bi] = 1;
        sh_idx = bi;
    }
    __syncthreads();

    const int idx = sh_idx;
    const float sel = g_nodes[((size_t)n * S_ + idx) * D_ + tid];
    g_prev[n * D_ + tid] = sel;
    if (t == 0) g_first[n * D_ + tid] = sel;
}

// ---------------- host orchestration ------------------------------------------
static inline void gemm(const float* A, const float* B, const float* bias,
                        float* C, int M, int N, int K, int relu)
{
    dim3 grid(N / 64, M / 64);
    sgemm_kernel<<<grid, 256>>>(A, B, bias, C, M, N, K, relu);
}

extern "C" void kernel_launch(void* const* d_in, const int* in_sizes, int n_in,
                              void* d_out, int out_size)
{
    const float* x      = (const float*)d_in[0];
    const int*   mask   = (const int*)d_in[1];
    const float* qkv_w  = (const float*)d_in[2];
    const float* qkv_b  = (const float*)d_in[3];
    const float* out_w  = (const float*)d_in[4];
    const float* out_b  = (const float*)d_in[5];
    const float* ff1_w  = (const float*)d_in[6];
    const float* ff1_b  = (const float*)d_in[7];
    const float* ff2_w  = (const float*)d_in[8];
    const float* ff2_b  = (const float*)d_in[9];
    const float* ln1_s  = (const float*)d_in[10];
    const float* ln1_b  = (const float*)d_in[11];
    const float* ln2_s  = (const float*)d_in[12];
    const float* ln2_b  = (const float*)d_in[13];
    const float* v1     = (const float*)d_in[14];
    const float* v2     = (const float*)d_in[15];
    const float* w_gq   = (const float*)d_in[16];
    const float* w_gk   = (const float*)d_in[17];
    const float* w_gv   = (const float*)d_in[18];
    const float* w_go   = (const float*)d_in[19];
    const float* b_go   = (const float*)d_in[20];
    const float* w_pq   = (const float*)d_in[21];
    const float* w_pk   = (const float*)d_in[22];

    float *ph, *pqkv, *pattn, *pff, *ptmp, *pnodes, *pgk, *pgv, *ppk, *pgraph, *pqgraph;
    cudaGetSymbolAddress((void**)&ph,      g_h);
    cudaGetSymbolAddress((void**)&pqkv,    g_qkv);
    cudaGetSymbolAddress((void**)&pattn,   g_attn);
    cudaGetSymbolAddress((void**)&pff,     g_ff);
    cudaGetSymbolAddress((void**)&ptmp,    g_tmp);
    cudaGetSymbolAddress((void**)&pnodes,  g_nodes);
    cudaGetSymbolAddress((void**)&pgk,     g_gk);
    cudaGetSymbolAddress((void**)&pgv,     g_gv);
    cudaGetSymbolAddress((void**)&ppk,     g_pk);
    cudaGetSymbolAddress((void**)&pgraph,  g_graph);
    cudaGetSymbolAddress((void**)&pqgraph, g_qgraph);

    // ---------------- encoder ----------------
    const float* hin = x;
    for (int i = 0; i < NL_; i++) {
        gemm(hin, qkv_w + (size_t)i * D_ * 3 * D_, qkv_b + i * 3 * D_,
             pqkv, SN_, 3 * D_, D_, 0);
        enc_attn_kernel<<<N_ * H_, 128>>>(pqkv, mask, pattn);
        gemm(pattn, out_w + (size_t)i * D_ * D_, out_b + i * D_,
             ptmp, SN_, D_, D_, 0);
        add_ln_kernel<<<SN_, 256>>>(hin, ptmp, ln1_s + i * D_, ln1_b + i * D_, ph);
        gemm(ph, ff1_w + (size_t)i * D_ * FF_, ff1_b + i * FF_,
             pff, SN_, FF_, D_, 1);
        gemm(pff, ff2_w + (size_t)i * FF_ * D_, ff2_b + i * D_,
             ptmp, SN_, D_, FF_, 0);
        add_ln_kernel<<<SN_, 256>>>(ph, ptmp, ln2_s + i * D_, ln2_b + i * D_, ph);
        hin = ph;
    }

    // ---------------- decode precompute ----------------
    transpose_kernel<<<SN_, 256>>>(ph);
    mean_kernel<<<N_, 256>>>();
    gemm(pnodes, w_gk, nullptr, pgk, SN_, D_, D_, 0);
    gemm(pnodes, w_gv, nullptr, pgv, SN_, D_, D_, 0);
    gemm(pnodes, w_pk, nullptr, ppk, SN_, D_, D_, 0);
    gemm(pgraph, w_gq, nullptr, pqgraph, N_, D_, D_, 0);  // g_wq rows [0:D)

    decode_init_kernel<<<N_, 256>>>(v1, v2, mask, (float*)d_out);

    // ---------------- sequential greedy decode ----------------
    for (int t = 0; t < S_; t++)
        decode_step_kernel<<<N_, 256>>>(w_gq, w_go, b_go, w_pq, (float*)d_out, t);
}